// round 5
// baseline (speedup 1.0000x reference)
#include <cuda_runtime.h>

// Problem dims
#define Bsz 4
#define Cin 8
#define Dd 48
#define Hh 128
#define Ww 160
#define HW (Hh*Ww)            // 20480
#define CH_STRIDE (Dd*HW)     // 983040
#define B_STRIDE (Cin*CH_STRIDE)

typedef unsigned long long ull;

// Fused, BN-folded, f32x2-pre-duplicated weights.
// layout: A0[o][c] (16x8) @0, C0[16] @128, A1T[o][j] (16x8, TRANSPOSED) @144,
//         C1[8] @272, W2[8] @280, B2 @288
__device__ ull g_fw[289];

__device__ __forceinline__ ull pack2same(float f) {
    unsigned u = __float_as_uint(f);
    return (((ull)u) << 32) | (ull)u;
}

__global__ void pw_setup_kernel(const float* __restrict__ w0, const float* __restrict__ g0,
                                const float* __restrict__ b0, const float* __restrict__ m0,
                                const float* __restrict__ v0,
                                const float* __restrict__ w1, const float* __restrict__ g1,
                                const float* __restrict__ b1, const float* __restrict__ m1,
                                const float* __restrict__ v1,
                                const float* __restrict__ w2, const float* __restrict__ b2) {
    int t = threadIdx.x;
    if (t < 16) {
        float s = g0[t] * rsqrtf(v0[t] + 1e-5f);
        #pragma unroll
        for (int c = 0; c < 8; c++) g_fw[t * 8 + c] = pack2same(w0[t * 8 + c] * s);
        g_fw[128 + t] = pack2same(b0[t] - m0[t] * s);
    } else if (t < 24) {
        int j = t - 16;                       // layer-1 output channel
        float s = g1[j] * rsqrtf(v1[j] + 1e-5f);
        // transposed: A1T[o*8 + j] = w1[j][o] * s
        #pragma unroll
        for (int o = 0; o < 16; o++) g_fw[144 + o * 8 + j] = pack2same(w1[j * 16 + o] * s);
        g_fw[272 + j] = pack2same(b1[j] - m1[j] * s);
    } else if (t < 32) {
        g_fw[280 + (t - 24)] = pack2same(w2[t - 24]);
    } else if (t == 32) {
        g_fw[288] = pack2same(b2[0]);
    }
}

// ---- packed f32x2 helpers (Blackwell: ptxas never auto-fuses; must use PTX) ----
__device__ __forceinline__ ull ffma2(ull a, ull b, ull c) {
    ull d;
    asm("fma.rn.f32x2 %0, %1, %2, %3;" : "=l"(d) : "l"(a), "l"(b), "l"(c));
    return d;
}
__device__ __forceinline__ float lo_f(ull a) { return __uint_as_float((unsigned)a); }
__device__ __forceinline__ float hi_f(ull a) { return __uint_as_float((unsigned)(a >> 32)); }
__device__ __forceinline__ ull mk2(float lo, float hi) {
    return (((ull)__float_as_uint(hi)) << 32) | (ull)__float_as_uint(lo);
}
__device__ __forceinline__ ull relu2(ull a) {
    return mk2(fmaxf(lo_f(a), 0.0f), fmaxf(hi_f(a), 0.0f));
}
__device__ __forceinline__ ull max2(ull a, ull b) {
    return mk2(fmaxf(lo_f(a), lo_f(b)), fmaxf(hi_f(a), hi_f(b)));
}

// Block = 128 threads. Warp w owns depth slice [12w, 12w+12); one voxel-pair
// per thread per iteration (small live set -> no spills at the 80-reg cap).
// Layer-1 accumulated incrementally (streamed h, A1 transposed).
// Max over d on pre-sigmoid logits (sigmoid monotone); smem reduce; 1 sigmoid.
__global__ __launch_bounds__(128, 6) void pw_main_kernel(const float* __restrict__ x,
                                                         float* __restrict__ out) {
    __shared__ ull sw[289];
    __shared__ ull red[128];
    for (int i = threadIdx.x; i < 289; i += 128) sw[i] = g_fw[i];
    __syncthreads();

    const int lane = threadIdx.x & 31;
    const int ds   = threadIdx.x >> 5;           // 0..3
    const int pidx = blockIdx.x * 32 + lane;     // global pair index, 0..40959
    const int wp   = pidx % 80;
    const int hh   = (pidx / 80) & (Hh - 1);
    const int bb   = pidx / (80 * Hh);

    const float* base = x + (size_t)bb * B_STRIDE + (size_t)hh * Ww + wp * 2
                          + (size_t)ds * 12 * HW;

    ull mx = pack2same(-3.0e38f);

    #pragma unroll 1
    for (int d = 0; d < 12; d++) {
        const float* p = base + (size_t)d * HW;

        ull xv[8];
        #pragma unroll
        for (int c = 0; c < 8; c++)
            xv[c] = *(const ull*)(p + c * CH_STRIDE);

        // layer-1 accumulators (biases), streamed over layer-0 outputs
        ull acc[8];
        #pragma unroll
        for (int j = 0; j < 8; j++) acc[j] = sw[272 + j];

        #pragma unroll
        for (int o = 0; o < 16; o++) {
            ull a0 = sw[128 + o];
            #pragma unroll
            for (int c = 0; c < 8; c++)
                a0 = ffma2(sw[o * 8 + c], xv[c], a0);
            ull h = relu2(a0);
            #pragma unroll
            for (int j = 0; j < 8; j++)
                acc[j] = ffma2(sw[144 + o * 8 + j], h, acc[j]);
        }

        ull s = sw[288];
        #pragma unroll
        for (int j = 0; j < 8; j++)
            s = ffma2(sw[280 + j], relu2(acc[j]), s);

        mx = max2(mx, s);
    }

    red[threadIdx.x] = mx;
    __syncthreads();

    if (threadIdx.x < 32) {
        ull m = max2(max2(red[lane], red[lane + 32]),
                     max2(red[lane + 64], red[lane + 96]));
        float r0 = 1.0f / (1.0f + __expf(-lo_f(m)));
        float r1 = 1.0f / (1.0f + __expf(-hi_f(m)));
        float2* po = (float2*)(out + (size_t)bb * HW + (size_t)hh * Ww + wp * 2);
        *po = make_float2(r0, r1);
    }
}

extern "C" void kernel_launch(void* const* d_in, const int* in_sizes, int n_in,
                              void* d_out, int out_size) {
    const float* x1 = (const float*)d_in[0];
    const float* w0 = (const float*)d_in[1];
    const float* g0 = (const float*)d_in[2];
    const float* b0 = (const float*)d_in[3];
    const float* m0 = (const float*)d_in[4];
    const float* v0 = (const float*)d_in[5];
    const float* w1 = (const float*)d_in[6];
    const float* g1 = (const float*)d_in[7];
    const float* b1 = (const float*)d_in[8];
    const float* m1 = (const float*)d_in[9];
    const float* v1 = (const float*)d_in[10];
    const float* w2 = (const float*)d_in[11];
    const float* b2 = (const float*)d_in[12];
    float* out = (float*)d_out;

    pw_setup_kernel<<<1, 64>>>(w0, g0, b0, m0, v0, w1, g1, b1, m1, v1, w2, b2);

    // 40960 pairs / 32 per block = 1280 blocks, 128 threads each
    pw_main_kernel<<<1280, 128>>>(x1, out);
}

// round 6
// speedup vs baseline: 8.8892x; 8.8892x over previous
#include <cuda_runtime.h>

// Problem dims
#define Bsz 4
#define Cin 8
#define Dd 48
#define Hh 128
#define Ww 160
#define HW (Hh*Ww)            // 20480
#define CH_STRIDE (Dd*HW)     // 983040
#define B_STRIDE (Cin*CH_STRIDE)

typedef unsigned long long ull;

// Fused, BN-folded, f32x2-pre-duplicated weights.
// layout: A0[o][c] (16x8) @0, C0[16] @128, A1T[o][j] (16x8, TRANSPOSED) @144,
//         C1[8] @272, W2[8] @280, B2 @288
__device__ ull g_fw[289];

__device__ __forceinline__ ull pack2same(float f) {
    unsigned u = __float_as_uint(f);
    return (((ull)u) << 32) | (ull)u;
}

__global__ void pw_setup_kernel(const float* __restrict__ w0, const float* __restrict__ g0,
                                const float* __restrict__ b0, const float* __restrict__ m0,
                                const float* __restrict__ v0,
                                const float* __restrict__ w1, const float* __restrict__ g1,
                                const float* __restrict__ b1, const float* __restrict__ m1,
                                const float* __restrict__ v1,
                                const float* __restrict__ w2, const float* __restrict__ b2) {
    int t = threadIdx.x;
    if (t < 16) {
        float s = g0[t] * rsqrtf(v0[t] + 1e-5f);
        #pragma unroll
        for (int c = 0; c < 8; c++) g_fw[t * 8 + c] = pack2same(w0[t * 8 + c] * s);
        g_fw[128 + t] = pack2same(b0[t] - m0[t] * s);
    } else if (t < 24) {
        int j = t - 16;                       // layer-1 output channel
        float s = g1[j] * rsqrtf(v1[j] + 1e-5f);
        // transposed: A1T[o*8 + j] = w1[j][o] * s
        #pragma unroll
        for (int o = 0; o < 16; o++) g_fw[144 + o * 8 + j] = pack2same(w1[j * 16 + o] * s);
        g_fw[272 + j] = pack2same(b1[j] - m1[j] * s);
    } else if (t < 32) {
        g_fw[280 + (t - 24)] = pack2same(w2[t - 24]);
    } else if (t == 32) {
        g_fw[288] = pack2same(b2[0]);
    }
}

// ---- packed f32x2 helpers (Blackwell: ptxas never auto-fuses; must use PTX) ----
__device__ __forceinline__ ull ffma2(ull a, ull b, ull c) {
    ull d;
    asm("fma.rn.f32x2 %0, %1, %2, %3;" : "=l"(d) : "l"(a), "l"(b), "l"(c));
    return d;
}
// Pinned weight load: volatile ld.shared cannot be hoisted by ptxas, so the
// weight register lives exactly one instruction. This is the anti-spill lever.
__device__ __forceinline__ ull lds_w(unsigned swbase, int idx) {
    ull v;
    asm volatile("ld.shared.b64 %0, [%1];" : "=l"(v) : "r"(swbase + idx * 8));
    return v;
}
__device__ __forceinline__ float lo_f(ull a) { return __uint_as_float((unsigned)a); }
__device__ __forceinline__ float hi_f(ull a) { return __uint_as_float((unsigned)(a >> 32)); }
__device__ __forceinline__ ull mk2(float lo, float hi) {
    return (((ull)__float_as_uint(hi)) << 32) | (ull)__float_as_uint(lo);
}
__device__ __forceinline__ ull relu2(ull a) {
    return mk2(fmaxf(lo_f(a), 0.0f), fmaxf(hi_f(a), 0.0f));
}
__device__ __forceinline__ ull max2(ull a, ull b) {
    return mk2(fmaxf(lo_f(a), lo_f(b)), fmaxf(hi_f(a), hi_f(b)));
}

// Block = 128 threads. Warp w owns depth slice [12w, 12w+12); one voxel-pair
// per thread per iteration. All weight LDS pinned at point-of-use.
// Max over d on pre-sigmoid logits (sigmoid monotone); smem reduce; 1 sigmoid.
__global__ __launch_bounds__(128, 5) void pw_main_kernel(const float* __restrict__ x,
                                                         float* __restrict__ out) {
    __shared__ ull sw[289];
    __shared__ ull red[128];
    for (int i = threadIdx.x; i < 289; i += 128) sw[i] = g_fw[i];
    __syncthreads();

    const unsigned swb = (unsigned)__cvta_generic_to_shared(sw);

    const int lane = threadIdx.x & 31;
    const int ds   = threadIdx.x >> 5;           // 0..3
    const int pidx = blockIdx.x * 32 + lane;     // global pair index, 0..40959
    const int wp   = pidx % 80;
    const int hh   = (pidx / 80) & (Hh - 1);
    const int bb   = pidx / (80 * Hh);

    const float* base = x + (size_t)bb * B_STRIDE + (size_t)hh * Ww + wp * 2
                          + (size_t)ds * 12 * HW;

    ull mx = pack2same(-3.0e38f);

    #pragma unroll 1
    for (int d = 0; d < 12; d++) {
        const float* p = base + (size_t)d * HW;

        ull xv[8];
        #pragma unroll
        for (int c = 0; c < 8; c++)
            xv[c] = *(const ull*)(p + c * CH_STRIDE);

        // layer-1 accumulators (biases), streamed over layer-0 outputs
        ull acc[8];
        #pragma unroll
        for (int j = 0; j < 8; j++) acc[j] = lds_w(swb, 272 + j);

        #pragma unroll
        for (int o = 0; o < 16; o++) {
            ull a0 = lds_w(swb, 128 + o);
            #pragma unroll
            for (int c = 0; c < 8; c++)
                a0 = ffma2(lds_w(swb, o * 8 + c), xv[c], a0);
            ull h = relu2(a0);
            #pragma unroll
            for (int j = 0; j < 8; j++)
                acc[j] = ffma2(lds_w(swb, 144 + o * 8 + j), h, acc[j]);
        }

        ull s = lds_w(swb, 288);
        #pragma unroll
        for (int j = 0; j < 8; j++)
            s = ffma2(lds_w(swb, 280 + j), relu2(acc[j]), s);

        mx = max2(mx, s);
    }

    red[threadIdx.x] = mx;
    __syncthreads();

    if (threadIdx.x < 32) {
        ull m = max2(max2(red[lane], red[lane + 32]),
                     max2(red[lane + 64], red[lane + 96]));
        float r0 = 1.0f / (1.0f + __expf(-lo_f(m)));
        float r1 = 1.0f / (1.0f + __expf(-hi_f(m)));
        float2* po = (float2*)(out + (size_t)bb * HW + (size_t)hh * Ww + wp * 2);
        *po = make_float2(r0, r1);
    }
}

extern "C" void kernel_launch(void* const* d_in, const int* in_sizes, int n_in,
                              void* d_out, int out_size) {
    const float* x1 = (const float*)d_in[0];
    const float* w0 = (const float*)d_in[1];
    const float* g0 = (const float*)d_in[2];
    const float* b0 = (const float*)d_in[3];
    const float* m0 = (const float*)d_in[4];
    const float* v0 = (const float*)d_in[5];
    const float* w1 = (const float*)d_in[6];
    const float* g1 = (const float*)d_in[7];
    const float* b1 = (const float*)d_in[8];
    const float* m1 = (const float*)d_in[9];
    const float* v1 = (const float*)d_in[10];
    const float* w2 = (const float*)d_in[11];
    const float* b2 = (const float*)d_in[12];
    float* out = (float*)d_out;

    pw_setup_kernel<<<1, 64>>>(w0, g0, b0, m0, v0, w1, g1, b1, m1, v1, w2, b2);

    // 40960 pairs / 32 per block = 1280 blocks, 128 threads each
    pw_main_kernel<<<1280, 128>>>(x1, out);
}